// round 14
// baseline (speedup 1.0000x reference)
#include <cuda_runtime.h>

#define NCH 4
#define WIDTH 4096
#define HEIGHT 4096
#define NPIX (WIDTH * HEIGHT)          // 16777216 per channel
#define NTILES 64                      // 8x8
#define NBINS 256
#define CLIPV 40960                    // int(40.0 * 512*512 / 256)
#define LUTF 0.000972747802734375f     // 255 / 2^18, exact in binary
#define INV255 (1.0f / 255.0f)
#define KMAX_BLOCKS 148                // 1 per SM; grid-stride over 2048 tiles

// ------------- persistent device scratch: self-cleaning across graph replays ---------
static __device__ unsigned g_minb1[NCH] = {0x7f800000u, 0x7f800000u, 0x7f800000u, 0x7f800000u};
static __device__ unsigned g_maxb1[NCH];                 // zero-init
static __device__ unsigned g_mcnt[NCH];                  // zero-init
static __device__ unsigned g_ctr1, g_ctr2;               // zero-init, wrap via atomicInc
static __device__ float    g_sc1[NCH], g_off1[NCH];      // bin = trunc(a*sc + off)
static __device__ int      g_cond1[NCH];
static __device__ unsigned g_hist[NCH * NTILES * NBINS]; // zero-init; re-zeroed in k_out
static __device__ float    g_lut[NCH * NTILES * NBINS];  // exact integers 0..255
static __device__ unsigned g_maxb2[NCH];                 // zero-init; max of eq (0..255)
static __device__ unsigned g_skip[NCH];                  // bin-255 present -> emax == 255 exact
static __device__ float    g_A[NCH];                     // out = fmaf(eq, A, 1/255) for masked
static __device__ unsigned char g_xb[(size_t)NCH * NPIX]; // quantized bin per pixel

// ---------------- K1: masked min/max/count + fused finalize (last block) -------------
__global__ __launch_bounds__(256) void k_minmax1(const float* __restrict__ X) {
    int c = blockIdx.x >> 10;   // 1024 blocks per channel
    const float4* p = reinterpret_cast<const float4*>(X) + (size_t)blockIdx.x * 4096u;
    float lmin = __uint_as_float(0x7f800000u);
    float lmax = 0.0f;
    unsigned cnt = 0u;
#pragma unroll 4
    for (int i = 0; i < 16; ++i) {
        float4 v = p[threadIdx.x + i * 256];
        if (v.x > 0.0f) { ++cnt; lmin = fminf(lmin, v.x); lmax = fmaxf(lmax, v.x); }
        if (v.y > 0.0f) { ++cnt; lmin = fminf(lmin, v.y); lmax = fmaxf(lmax, v.y); }
        if (v.z > 0.0f) { ++cnt; lmin = fminf(lmin, v.z); lmax = fmaxf(lmax, v.z); }
        if (v.w > 0.0f) { ++cnt; lmin = fminf(lmin, v.w); lmax = fmaxf(lmax, v.w); }
    }
    for (int o = 16; o; o >>= 1) {
        lmin = fminf(lmin, __shfl_xor_sync(0xffffffffu, lmin, o));
        lmax = fmaxf(lmax, __shfl_xor_sync(0xffffffffu, lmax, o));
        cnt += __shfl_xor_sync(0xffffffffu, cnt, o);
    }
    __shared__ float smn[8], smx[8];
    __shared__ unsigned scn[8];
    int w = threadIdx.x >> 5;
    if ((threadIdx.x & 31) == 0) { smn[w] = lmin; smx[w] = lmax; scn[w] = cnt; }
    __syncthreads();
    if (threadIdx.x == 0) {
        for (int i = 1; i < 8; ++i) {
            lmin = fminf(lmin, smn[i]); lmax = fmaxf(lmax, smx[i]); cnt += scn[i];
        }
        atomicMin(&g_minb1[c], __float_as_uint(lmin));   // nonneg floats: uint order == float order
        atomicMax(&g_maxb1[c], __float_as_uint(lmax));
        atomicAdd(&g_mcnt[c], cnt);
        __threadfence();
        if (atomicInc(&g_ctr1, 4095u) == 4095u) {        // last arriving block; ctr auto-wraps to 0
            for (int ch = 0; ch < NCH; ++ch) {
                unsigned mb = atomicAdd(&g_minb1[ch], 0u);    // L2-coherent reads
                unsigned xb = atomicAdd(&g_maxb1[ch], 0u);
                unsigned mc = atomicAdd(&g_mcnt[ch], 0u);
                float mx = __uint_as_float(xb);
                float mn = __uint_as_float(mb);
                g_cond1[ch] = (mc > 0u) && (mx > 0.0f);
                double sc = 255.0 / fmax((double)mx - (double)mn, 1e-12);
                g_sc1[ch]  = (float)sc;
                g_off1[ch] = (float)(-(double)mn * sc);
                g_minb1[ch] = 0x7f800000u;               // reset for next replay
                g_maxb1[ch] = 0u;                        // (g_mcnt still needed later)
            }
        }
    }
}

// ---------------- K2: normalize, quantize, write bins, per-warp tile histograms ------
__device__ __forceinline__ unsigned binone(float a, float sc, float off, int cond) {
    float xm = cond ? fmaf(a, sc, off) : 0.0f;
    float x  = a > 0.0f ? xm : a * 255.0f;
    return __float2uint_rz(fminf(x, 255.0f));   // F2I.U32 saturates negatives to 0
}

__global__ __launch_bounds__(256) void k_binhist(const float* __restrict__ X) {
    int tx = blockIdx.x, by = blockIdx.y, c = blockIdx.z;
    int tile = (by >> 3) * 8 + tx;
    __shared__ unsigned sh[8][NBINS];                    // per-warp sub-histograms
#pragma unroll
    for (int w = 0; w < 8; ++w) sh[w][threadIdx.x] = 0u;
    __syncthreads();
    unsigned* mysh = sh[threadIdx.x >> 5];
    float sc = g_sc1[c], off = g_off1[c];
    int cond = g_cond1[c];
    size_t cb = (size_t)c * NPIX;
#pragma unroll 4
    for (int i = 0; i < 32; ++i) {
        int lin = i * 256 + threadIdx.x;
        int r = lin >> 7, c4 = lin & 127;
        size_t idx = cb + (size_t)(by * 64 + r) * WIDTH + tx * 512 + c4 * 4;
        float4 v = __ldcs(reinterpret_cast<const float4*>(X + idx));
        unsigned b0 = binone(v.x, sc, off, cond);
        unsigned b1 = binone(v.y, sc, off, cond);
        unsigned b2 = binone(v.z, sc, off, cond);
        unsigned b3 = binone(v.w, sc, off, cond);
        atomicAdd(&mysh[b0], 1u);
        atomicAdd(&mysh[b1], 1u);
        atomicAdd(&mysh[b2], 1u);
        atomicAdd(&mysh[b3], 1u);
        *reinterpret_cast<unsigned*>(g_xb + idx) = b0 | (b1 << 8) | (b2 << 16) | (b3 << 24);
    }
    __syncthreads();
    unsigned tot = 0u;
#pragma unroll
    for (int w = 0; w < 8; ++w) tot += sh[w][threadIdx.x];
    atomicAdd(&g_hist[(c * NTILES + tile) * NBINS + threadIdx.x], tot);
}

// ---------------- K3: fused mean-of-nonzeros + per-tile clip/redistribute/scan/LUT ----
__global__ __launch_bounds__(256) void k_lutmean() {
    int c = blockIdx.x >> 6, tile = blockIdx.x & 63, b = threadIdx.x;
    int lane = b & 31, wrp = b >> 5;
    const unsigned* hch = g_hist + c * NTILES * NBINS;

    // channel-wide mean of nonzero bins (recomputed redundantly per block; L2-hit reads)
    unsigned cnt = 0u;
#pragma unroll 8
    for (int t = 0; t < NTILES; ++t) cnt += hch[t * NBINS + b];
    unsigned msc = b ? cnt : 0u;
    unsigned long long msw = (unsigned long long)msc * (unsigned)b;
    for (int o = 16; o; o >>= 1) {
        msc += __shfl_xor_sync(0xffffffffu, msc, o);
        msw += __shfl_xor_sync(0xffffffffu, msw, o);
    }
    __shared__ unsigned s_c[8];
    __shared__ unsigned long long s_w[8];
    if (lane == 0) { s_c[wrp] = msc; s_w[wrp] = msw; }
    __syncthreads();
    unsigned nz = 0u; unsigned long long ws = 0ull;
#pragma unroll
    for (int i = 0; i < 8; ++i) { nz += s_c[i]; ws += s_w[i]; }
    int mean = nz ? (int)(ws / nz) : 0;

    // emax short-circuit: redistribution conserves totals -> cdf[255]=area -> every
    // tile's LUT[255]==255 -> any genuine bin-255 pixel has eq == 255 exactly, and
    // eq <= 255 everywhere. Genuine requires mean != 255 (mean-fill aliases bin 255).
    if (b == 255 && tile == 0) {
        int skip = (cnt > 0u) && (mean != 255);
        g_skip[c] = (unsigned)skip;
        if (skip) g_A[c] = (float)((254.0 / 255.0) / 255.0);
    }

    // per-tile clip + redistribute
    int h  = (int)hch[tile * NBINS + b];
    int h0 = (int)hch[tile * NBINS];
    if (nz > 0u) {                 // zero pixels were filled with mean_nz before histogram
        if (b == 0) h = 0;
        if (b == mean) h += h0;
    }
    int hc = min(h, CLIPV);
    int over = h - hc;
    for (int o = 16; o; o >>= 1) over += __shfl_xor_sync(0xffffffffu, over, o);
    __shared__ int s_e[8];
    if (lane == 0) s_e[wrp] = over;
    __syncthreads();
    int excess = 0;
#pragma unroll
    for (int i = 0; i < 8; ++i) excess += s_e[i];
    int batch = excess >> 8;
    int residual = excess & 255;
    int step = residual > 0 ? max(256 / residual, 1) : 256;
    int resadd = ((b % step) == 0 && (b / step) < residual) ? 1 : 0;
    int hf = hc + batch + resadd;

    // inclusive scan over 256 bins: warp shuffle scan + cross-warp offsets
    int x = hf;
#pragma unroll
    for (int o = 1; o < 32; o <<= 1) {
        int y = __shfl_up_sync(0xffffffffu, x, o);
        if (lane >= o) x += y;
    }
    __shared__ int s_t[8];
    if (lane == 31) s_t[wrp] = x;
    __syncthreads();
    int add = 0;
#pragma unroll
    for (int i = 0; i < 8; ++i) add += (i < wrp) ? s_t[i] : 0;
    int cdf = x + add;

    float lut = rintf((float)cdf * LUTF);     // rintf == round-half-even == jnp.round
    lut = fminf(fmaxf(lut, 0.0f), 255.0f);
    g_lut[(c * NTILES + tile) * NBINS + b] = lut;
}

// ---------------- combined 4-point stencil table: one uint per (x-slot, bin) ----------
// sl[s][bin] packs (v00, v10, v01, v11) as exact uchar LUT values.
// bin-0 entry forced to 0: reference forces eq=0 there (masked bin-0 -> FLO via fmaf).
__device__ __forceinline__ void load_cmb(unsigned (*sl)[NBINS], int c, int tx, int by) {
    int ty = by >> 3;
    int y0 = ((by & 7) < 4) ? max(ty - 1, 0) : ty;
    int y1 = min(y0 + 1, 7);
    const float* L0 = g_lut + ((c * 8 + y0) * 8) * NBINS;
    const float* L1 = g_lut + ((c * 8 + y1) * 8) * NBINS;
    int b = threadIdx.x;   // 256 threads == 256 bins
#pragma unroll
    for (int s = 0; s < 2; ++s) {
        int xa = min(max(tx - 1 + s, 0), 7);
        int xb_ = min(tx + s, 7);
        unsigned v00 = (unsigned)L0[xa * NBINS + b];
        unsigned v10 = (unsigned)L1[xa * NBINS + b];
        unsigned v01 = (unsigned)L0[xb_ * NBINS + b];
        unsigned v11 = (unsigned)L1[xb_ * NBINS + b];
        unsigned pk = v00 | (v10 << 8) | (v01 << 16) | (v11 << 24);
        sl[s][b] = b ? pk : 0u;
    }
}

// magic-number byte->float unpack with delta trick: the magic bias cancels exactly in
// corner differences (all magic floats are exact integers), so only 2 of 4 corners
// need the bias subtraction. Bit-identical to the 4-subtraction version.
__device__ __forceinline__ float eq4m(unsigned w, float wx, float wy) {
    float m00 = __uint_as_float(__byte_perm(w, 0x4B000000u, 0x7440));
    float m10 = __uint_as_float(__byte_perm(w, 0x4B000000u, 0x7441));
    float m01 = __uint_as_float(__byte_perm(w, 0x4B000000u, 0x7442));
    float m11 = __uint_as_float(__byte_perm(w, 0x4B000000u, 0x7443));
    float v00 = m00 - 8388608.0f;
    float v01 = m01 - 8388608.0f;
    float ya = fmaf(wy, m10 - m00, v00);
    float yb = fmaf(wy, m11 - m01, v01);
    return fmaf(wx, yb - ya, ya);
}

// ---------------- K4: channel max of eq; grid-stride, near-empty when skip ------------
__global__ __launch_bounds__(256) void k_max() {
    for (unsigned t = blockIdx.x; t < 2048u; t += KMAX_BLOCKS) {
        int tx = t & 7, by = (t >> 3) & 63, c = t >> 9;
        if (g_skip[c]) continue;                          // emax proven == 255; A already set
        __shared__ unsigned sl[2][NBINS];
        load_cmb(sl, c, tx, by);
        __syncthreads();
        int c4 = threadIdx.x & 127;
        int colb = tx * 512 + c4 * 4;
        int m0 = (colb - 256) >> 9;                       // unclamped floor of fx
        float wx0 = ((float)colb - 255.5f) * (1.0f / 512.0f) - (float)m0;   // exact
        float wx1 = wx0 + 0.001953125f;
        float wx2 = wx0 + 0.00390625f;
        float wx3 = wx0 + 0.005859375f;
        int s = min(max(m0, 0), 7) - tx + 1;              // slot in {0,1}
        const unsigned* slp = sl[s];
        int r0 = threadIdx.x >> 7;
        int row0 = by * 64 + r0;
        float fy0 = ((float)row0 + 0.5f) * (1.0f / 512.0f) - 0.5f;
        float wy = fy0 - floorf(fy0);                     // exact multiple of 2^-10
        size_t base = (size_t)c * NPIX + (size_t)row0 * WIDTH + colb;
        float emax = 0.0f;
#pragma unroll 8
        for (int i = 0; i < 32; ++i) {
            unsigned qw = *reinterpret_cast<const unsigned*>(g_xb + base + (size_t)i * (2 * WIDTH));
            unsigned q0 = qw & 0xffu, q1 = (qw >> 8) & 0xffu;
            unsigned q2 = (qw >> 16) & 0xffu, q3 = qw >> 24;
            float e0 = eq4m(slp[q0], wx0, wy);
            float e1 = eq4m(slp[q1], wx1, wy);
            float e2 = eq4m(slp[q2], wx2, wy);
            float e3 = eq4m(slp[q3], wx3, wy);
            emax = fmaxf(emax, fmaxf(fmaxf(e0, e1), fmaxf(e2, e3)));
            wy += (1.0f / 256.0f);                        // exact; floor constant in block
        }
        for (int o = 16; o; o >>= 1)
            emax = fmaxf(emax, __shfl_xor_sync(0xffffffffu, emax, o));
        __shared__ float smx[8];
        int w = threadIdx.x >> 5;
        if ((threadIdx.x & 31) == 0) smx[w] = emax;
        __syncthreads();
        if (threadIdx.x == 0) {
            for (int i = 1; i < 8; ++i) emax = fmaxf(emax, smx[i]);
            atomicMax(&g_maxb2[c], __float_as_uint(emax));
        }
        __syncthreads();                                  // sl/smx reuse across tiles
    }
    if (threadIdx.x == 0) {
        __threadfence();
        if (atomicInc(&g_ctr2, KMAX_BLOCKS - 1u) == KMAX_BLOCKS - 1u) {  // last block
            for (int ch = 0; ch < NCH; ++ch) {
                if (!g_skip[ch]) {                        // skip channels: A set in k_lutmean
                    unsigned mc = atomicAdd(&g_mcnt[ch], 0u);
                    double mx = (double)__uint_as_float(atomicAdd(&g_maxb2[ch], 0u)) / 255.0;
                    int cond = (mc > 0u) && (mx > 0.0);
                    // vmin of the 2nd normalize is provably 0 whenever cond holds:
                    // out = eq * A + 1/255 for masked pixels.
                    g_A[ch] = cond ? (float)((254.0 / 255.0) / (255.0 * fmax(mx, 1e-12))) : 0.0f;
                }
                g_maxb2[ch] = 0u;                         // reset for next replay
                g_mcnt[ch]  = 0u;
            }
        }
    }
}

// ---------------- K5: recompute eq, final masked normalize, write output --------------
// 64 threads per row x 8 px (uint2) per thread per iteration.
__device__ __forceinline__ float4 out4(unsigned qw, const unsigned* slp,
                                       float wxb, float wy, float A) {
    unsigned q0 = qw & 0xffu, q1 = (qw >> 8) & 0xffu;
    unsigned q2 = (qw >> 16) & 0xffu, q3 = qw >> 24;
    float4 o;
    o.x = fmaf(eq4m(slp[q0], wxb, wy), A, INV255);
    o.y = fmaf(eq4m(slp[q1], wxb + 0.001953125f, wy), A, INV255);
    o.z = fmaf(eq4m(slp[q2], wxb + 0.00390625f, wy), A, INV255);
    o.w = fmaf(eq4m(slp[q3], wxb + 0.005859375f, wy), A, INV255);
    return o;
}

__device__ __forceinline__ void fix4(float4& o, unsigned qw, const float* Xp) {
    if ((qw - 0x01010101u) & ~qw & 0x80808080u) {         // rare: some byte==0 -> check mask
        float4 v = *reinterpret_cast<const float4*>(Xp);
        if (!(qw & 0xffu)       && !(v.x > 0.0f)) o.x = 0.0f;
        if (!(qw & 0xff00u)     && !(v.y > 0.0f)) o.y = 0.0f;
        if (!(qw & 0xff0000u)   && !(v.z > 0.0f)) o.z = 0.0f;
        if (!(qw & 0xff000000u) && !(v.w > 0.0f)) o.w = 0.0f;
    }
}

__global__ __launch_bounds__(256) void k_out(const float* __restrict__ X,
                                             float* __restrict__ out) {
    int tx = blockIdx.x, by = blockIdx.y, c = blockIdx.z;
    if (by < 8)                                           // re-zero g_hist for next replay
        g_hist[(c * NTILES + by * 8 + tx) * NBINS + threadIdx.x] = 0u;
    __shared__ unsigned sl[2][NBINS];
    load_cmb(sl, c, tx, by);
    __syncthreads();
    float A = g_A[c];
    int c6 = threadIdx.x & 63;
    int colb = tx * 512 + c6 * 8;
    int m0 = (colb - 256) >> 9;
    float wxb = ((float)colb - 255.5f) * (1.0f / 512.0f) - (float)m0;   // exact
    int s = min(max(m0, 0), 7) - tx + 1;
    const unsigned* slp = sl[s];
    int r0 = threadIdx.x >> 6;                            // 0..3
    int row0 = by * 64 + r0;
    float fy0 = ((float)row0 + 0.5f) * (1.0f / 512.0f) - 0.5f;
    float wy = fy0 - floorf(fy0);                         // exact multiple of 2^-10
    size_t base = (size_t)c * NPIX + (size_t)row0 * WIDTH + colb;
#pragma unroll 2
    for (int i = 0; i < 16; ++i) {
        size_t idx = base + (size_t)i * (4 * WIDTH);
        uint2 qq = *reinterpret_cast<const uint2*>(g_xb + idx);
        float4 oA = out4(qq.x, slp, wxb, wy, A);
        float4 oB = out4(qq.y, slp, wxb + 0.0078125f, wy, A);
        fix4(oA, qq.x, X + idx);
        fix4(oB, qq.y, X + idx + 4);
        __stcs(reinterpret_cast<float4*>(out + idx), oA);     // streaming: never re-read
        __stcs(reinterpret_cast<float4*>(out + idx + 4), oB);
        wy += (1.0f / 128.0f);                            // 4 rows per iter; exact
    }
}

// ---------------- launch --------------------------------------------------------------
extern "C" void kernel_launch(void* const* d_in, const int* in_sizes, int n_in,
                              void* d_out, int out_size) {
    const float* X = (const float*)d_in[0];
    float* out = (float*)d_out;
    (void)in_sizes; (void)n_in; (void)out_size;

    dim3 g(8, 64, NCH);
    k_minmax1<<<4096, 256>>>(X);       // + fused fin1 (last block)
    k_binhist<<<g, 256>>>(X);
    k_lutmean<<<NCH * NTILES, 256>>>();
    k_max<<<KMAX_BLOCKS, 256>>>();     // grid-stride; near no-op when skip; + fused fin2
    k_out<<<g, 256>>>(X, out);         // + hist re-zero
}

// round 15
// speedup vs baseline: 1.0584x; 1.0584x over previous
#include <cuda_runtime.h>

#define NCH 4
#define WIDTH 4096
#define HEIGHT 4096
#define NPIX (WIDTH * HEIGHT)          // 16777216 per channel
#define NTILES 64                      // 8x8
#define NBINS 256
#define CLIPV 40960                    // int(40.0 * 512*512 / 256)
#define LUTF 0.000972747802734375f     // 255 / 2^18, exact in binary
#define INV255 (1.0f / 255.0f)
#define LM_BLOCKS 256                  // k_lutmax grid: all-resident at 2/SM (148 SMs)

// ------------- persistent device scratch: self-cleaning across graph replays ---------
static __device__ unsigned g_minb1[NCH] = {0x7f800000u, 0x7f800000u, 0x7f800000u, 0x7f800000u};
static __device__ unsigned g_maxb1[NCH];                 // zero-init
static __device__ unsigned g_mcnt[NCH];                  // zero-init
static __device__ unsigned g_ctr1;                       // zero-init, wrap via atomicInc
static __device__ unsigned g_arr2, g_go2, g_done2;       // lutmax barrier (zero-init)
static __device__ float    g_sc1[NCH], g_off1[NCH];      // bin = trunc(a*sc + off)
static __device__ int      g_cond1[NCH];
static __device__ unsigned g_hist[NCH * NTILES * NBINS]; // zero-init; re-zeroed in k_lutmax B
static __device__ float    g_lut[NCH * NTILES * NBINS];  // exact integers 0..255
static __device__ unsigned g_maxb2[NCH];                 // zero-init; max of eq (0..255)
static __device__ unsigned g_skip[NCH];                  // bin-255 present -> emax == 255 exact
static __device__ float    g_A[NCH];                     // out = fmaf(eq, A, 1/255) for masked
static __device__ unsigned char g_xb[(size_t)NCH * NPIX]; // quantized bin per pixel

__device__ __forceinline__ void spin_until(volatile unsigned* flag) {
    while (*flag == 0u) __nanosleep(64);                 // L2 volatile poll, no atomics
}

// ---------------- K1: masked min/max/count + fused finalize (last block) -------------
__global__ __launch_bounds__(256) void k_minmax1(const float* __restrict__ X) {
    int c = blockIdx.x >> 10;   // 1024 blocks per channel
    const float4* p = reinterpret_cast<const float4*>(X) + (size_t)blockIdx.x * 4096u;
    float lmin = __uint_as_float(0x7f800000u);
    float lmax = 0.0f;
    unsigned cnt = 0u;
#pragma unroll 4
    for (int i = 0; i < 16; ++i) {
        float4 v = p[threadIdx.x + i * 256];
        if (v.x > 0.0f) { ++cnt; lmin = fminf(lmin, v.x); lmax = fmaxf(lmax, v.x); }
        if (v.y > 0.0f) { ++cnt; lmin = fminf(lmin, v.y); lmax = fmaxf(lmax, v.y); }
        if (v.z > 0.0f) { ++cnt; lmin = fminf(lmin, v.z); lmax = fmaxf(lmax, v.z); }
        if (v.w > 0.0f) { ++cnt; lmin = fminf(lmin, v.w); lmax = fmaxf(lmax, v.w); }
    }
    for (int o = 16; o; o >>= 1) {
        lmin = fminf(lmin, __shfl_xor_sync(0xffffffffu, lmin, o));
        lmax = fmaxf(lmax, __shfl_xor_sync(0xffffffffu, lmax, o));
        cnt += __shfl_xor_sync(0xffffffffu, cnt, o);
    }
    __shared__ float smn[8], smx[8];
    __shared__ unsigned scn[8];
    int w = threadIdx.x >> 5;
    if ((threadIdx.x & 31) == 0) { smn[w] = lmin; smx[w] = lmax; scn[w] = cnt; }
    __syncthreads();
    if (threadIdx.x == 0) {
        for (int i = 1; i < 8; ++i) {
            lmin = fminf(lmin, smn[i]); lmax = fmaxf(lmax, smx[i]); cnt += scn[i];
        }
        atomicMin(&g_minb1[c], __float_as_uint(lmin));   // nonneg floats: uint order == float order
        atomicMax(&g_maxb1[c], __float_as_uint(lmax));
        atomicAdd(&g_mcnt[c], cnt);
        __threadfence();
        if (atomicInc(&g_ctr1, 4095u) == 4095u) {        // last arriving block; ctr auto-wraps to 0
            for (int ch = 0; ch < NCH; ++ch) {
                unsigned mb = atomicAdd(&g_minb1[ch], 0u);    // L2-coherent reads
                unsigned xb = atomicAdd(&g_maxb1[ch], 0u);
                unsigned mc = atomicAdd(&g_mcnt[ch], 0u);
                float mx = __uint_as_float(xb);
                float mn = __uint_as_float(mb);
                g_cond1[ch] = (mc > 0u) && (mx > 0.0f);
                double sc = 255.0 / fmax((double)mx - (double)mn, 1e-12);
                g_sc1[ch]  = (float)sc;
                g_off1[ch] = (float)(-(double)mn * sc);
                g_minb1[ch] = 0x7f800000u;               // reset for next replay
                g_maxb1[ch] = 0u;                        // (g_mcnt still needed later)
            }
        }
    }
}

// ---------------- K2: normalize, quantize, write bins, tile histograms ---------------
__device__ __forceinline__ unsigned binone(float a, float sc, float off, int cond) {
    float xm = cond ? fmaf(a, sc, off) : 0.0f;
    float x  = a > 0.0f ? xm : a * 255.0f;
    return __float2uint_rz(fminf(x, 255.0f));   // F2I.U32 saturates negatives to 0
}

__global__ __launch_bounds__(256) void k_binhist(const float* __restrict__ X) {
    int tx = blockIdx.x, by = blockIdx.y, c = blockIdx.z;
    int tile = (by >> 3) * 8 + tx;
    __shared__ unsigned sh[NBINS];
    sh[threadIdx.x] = 0u;
    __syncthreads();
    float sc = g_sc1[c], off = g_off1[c];
    int cond = g_cond1[c];
    size_t cb = (size_t)c * NPIX;
#pragma unroll 4
    for (int i = 0; i < 32; ++i) {
        int lin = i * 256 + threadIdx.x;
        int r = lin >> 7, c4 = lin & 127;
        size_t idx = cb + (size_t)(by * 64 + r) * WIDTH + tx * 512 + c4 * 4;
        float4 v = __ldcs(reinterpret_cast<const float4*>(X + idx));
        unsigned b0 = binone(v.x, sc, off, cond);
        unsigned b1 = binone(v.y, sc, off, cond);
        unsigned b2 = binone(v.z, sc, off, cond);
        unsigned b3 = binone(v.w, sc, off, cond);
        atomicAdd(&sh[b0], 1u);
        atomicAdd(&sh[b1], 1u);
        atomicAdd(&sh[b2], 1u);
        atomicAdd(&sh[b3], 1u);
        *reinterpret_cast<unsigned*>(g_xb + idx) = b0 | (b1 << 8) | (b2 << 16) | (b3 << 24);
    }
    __syncthreads();
    atomicAdd(&g_hist[(c * NTILES + tile) * NBINS + threadIdx.x], sh[threadIdx.x]);
}

// ---------------- combined 4-point stencil table: one uint per (x-slot, bin) ----------
// sl[s][bin] packs (v00, v10, v01, v11) as exact uchar LUT values.
// bin-0 entry forced to 0: reference forces eq=0 there (masked bin-0 -> FLO via fmaf).
__device__ __forceinline__ void load_cmb(unsigned (*sl)[NBINS], int c, int tx, int by) {
    int ty = by >> 3;
    int y0 = ((by & 7) < 4) ? max(ty - 1, 0) : ty;
    int y1 = min(y0 + 1, 7);
    const float* L0 = g_lut + ((c * 8 + y0) * 8) * NBINS;
    const float* L1 = g_lut + ((c * 8 + y1) * 8) * NBINS;
    int b = threadIdx.x;   // 256 threads == 256 bins
#pragma unroll
    for (int s = 0; s < 2; ++s) {
        int xa = min(max(tx - 1 + s, 0), 7);
        int xb_ = min(tx + s, 7);
        unsigned v00 = (unsigned)L0[xa * NBINS + b];
        unsigned v10 = (unsigned)L1[xa * NBINS + b];
        unsigned v01 = (unsigned)L0[xb_ * NBINS + b];
        unsigned v11 = (unsigned)L1[xb_ * NBINS + b];
        unsigned pk = v00 | (v10 << 8) | (v01 << 16) | (v11 << 24);
        sl[s][b] = b ? pk : 0u;
    }
}

// magic-number byte->float unpack with delta trick: the magic bias cancels exactly in
// corner differences (all magic floats are exact integers), so only 2 of 4 corners
// need the bias subtraction. Bit-identical to the 4-subtraction version.
__device__ __forceinline__ float eq4m(unsigned w, float wx, float wy) {
    float m00 = __uint_as_float(__byte_perm(w, 0x4B000000u, 0x7440));
    float m10 = __uint_as_float(__byte_perm(w, 0x4B000000u, 0x7441));
    float m01 = __uint_as_float(__byte_perm(w, 0x4B000000u, 0x7442));
    float m11 = __uint_as_float(__byte_perm(w, 0x4B000000u, 0x7443));
    float v00 = m00 - 8388608.0f;
    float v01 = m01 - 8388608.0f;
    float ya = fmaf(wy, m10 - m00, v00);
    float yb = fmaf(wy, m11 - m01, v01);
    return fmaf(wx, yb - ya, ya);
}

// ---------------- K3+K4 fused: LUT build, tiny barrier, hist-rezero + emax + finalize -
__global__ __launch_bounds__(256, 2) void k_lutmax() {
    int c = blockIdx.x >> 6, tile = blockIdx.x & 63, b = threadIdx.x;
    int lane = b & 31, wrp = b >> 5;
    const unsigned* hch = g_hist + c * NTILES * NBINS;

    // channel-wide mean of nonzero bins (recomputed redundantly per block; L2-hit reads)
    unsigned cnt = 0u;
#pragma unroll 8
    for (int t = 0; t < NTILES; ++t) cnt += hch[t * NBINS + b];
    unsigned msc = b ? cnt : 0u;
    unsigned long long msw = (unsigned long long)msc * (unsigned)b;
    for (int o = 16; o; o >>= 1) {
        msc += __shfl_xor_sync(0xffffffffu, msc, o);
        msw += __shfl_xor_sync(0xffffffffu, msw, o);
    }
    __shared__ unsigned s_c[8];
    __shared__ unsigned long long s_w[8];
    if (lane == 0) { s_c[wrp] = msc; s_w[wrp] = msw; }
    __syncthreads();
    unsigned nz = 0u; unsigned long long ws = 0ull;
#pragma unroll
    for (int i = 0; i < 8; ++i) { nz += s_c[i]; ws += s_w[i]; }
    int mean = nz ? (int)(ws / nz) : 0;

    // emax short-circuit: redistribution conserves totals -> cdf[255]=area -> every
    // tile's LUT[255]==255 -> any genuine bin-255 pixel has eq == 255 exactly, and
    // eq <= 255 everywhere. Genuine requires mean != 255 (mean-fill aliases bin 255).
    if (b == 255 && tile == 0) {
        int skip = (cnt > 0u) && (mean != 255);
        g_skip[c] = (unsigned)skip;
        if (skip) g_A[c] = (float)((254.0 / 255.0) / 255.0);
    }

    // per-tile clip + redistribute
    int h  = (int)hch[tile * NBINS + b];
    int h0 = (int)hch[tile * NBINS];
    if (nz > 0u) {                 // zero pixels were filled with mean_nz before histogram
        if (b == 0) h = 0;
        if (b == mean) h += h0;
    }
    int hc = min(h, CLIPV);
    int over = h - hc;
    for (int o = 16; o; o >>= 1) over += __shfl_xor_sync(0xffffffffu, over, o);
    __shared__ int s_e[8];
    if (lane == 0) s_e[wrp] = over;
    __syncthreads();
    int excess = 0;
#pragma unroll
    for (int i = 0; i < 8; ++i) excess += s_e[i];
    int batch = excess >> 8;
    int residual = excess & 255;
    int step = residual > 0 ? max(256 / residual, 1) : 256;
    int resadd = ((b % step) == 0 && (b / step) < residual) ? 1 : 0;
    int hf = hc + batch + resadd;

    // inclusive scan over 256 bins: warp shuffle scan + cross-warp offsets
    int x = hf;
#pragma unroll
    for (int o = 1; o < 32; o <<= 1) {
        int y = __shfl_up_sync(0xffffffffu, x, o);
        if (lane >= o) x += y;
    }
    __shared__ int s_t[8];
    if (lane == 31) s_t[wrp] = x;
    __syncthreads();
    int add = 0;
#pragma unroll
    for (int i = 0; i < 8; ++i) add += (i < wrp) ? s_t[i] : 0;
    int cdf = x + add;

    float lut = rintf((float)cdf * LUTF);     // rintf == round-half-even == jnp.round
    lut = fminf(fmaxf(lut, 0.0f), 255.0f);
    g_lut[(c * NTILES + tile) * NBINS + b] = lut;

    // ---- device barrier (256 blocks all-resident at 2/SM; LUT phase is tiny) ----
    if (threadIdx.x == 0) {
        __threadfence();
        if (atomicInc(&g_arr2, LM_BLOCKS - 1u) == LM_BLOCKS - 1u) {
            __threadfence();
            atomicExch(&g_go2, 1u);
        }
        spin_until(&g_go2);
    }
    __syncthreads();
    __threadfence();                                     // acquire: g_lut/g_skip complete

    // ---- phase B: hist re-zero (all reads done) + emax fallback for non-skip ----
    g_hist[blockIdx.x * NBINS + threadIdx.x] = 0u;       // 65536 entries == 65536 threads
    __shared__ unsigned sl[2][NBINS];
    __shared__ float smx[8];
    for (unsigned t = blockIdx.x; t < 2048u; t += LM_BLOCKS) {
        int tx = t & 7, by = (int)(t >> 3) & 63, cc = (int)(t >> 9);
        if (g_skip[cc]) continue;                        // emax proven == 255; A already set
        load_cmb(sl, cc, tx, by);
        __syncthreads();
        int c4 = threadIdx.x & 127;
        int colb = tx * 512 + c4 * 4;
        int m0 = (colb - 256) >> 9;
        float wx0 = ((float)colb - 255.5f) * (1.0f / 512.0f) - (float)m0;   // exact
        float wx1 = wx0 + 0.001953125f;
        float wx2 = wx0 + 0.00390625f;
        float wx3 = wx0 + 0.005859375f;
        int s = min(max(m0, 0), 7) - tx + 1;
        const unsigned* slp = sl[s];
        int r0 = threadIdx.x >> 7;
        int row0 = by * 64 + r0;
        float fy0 = ((float)row0 + 0.5f) * (1.0f / 512.0f) - 0.5f;
        float wy = fy0 - floorf(fy0);                    // exact multiple of 2^-10
        size_t base = (size_t)cc * NPIX + (size_t)row0 * WIDTH + colb;
        float emax = 0.0f;
#pragma unroll 8
        for (int i = 0; i < 32; ++i) {
            unsigned qw = *reinterpret_cast<const unsigned*>(g_xb + base + (size_t)i * (2 * WIDTH));
            unsigned q0 = qw & 0xffu, q1 = (qw >> 8) & 0xffu;
            unsigned q2 = (qw >> 16) & 0xffu, q3 = qw >> 24;
            float e0 = eq4m(slp[q0], wx0, wy);
            float e1 = eq4m(slp[q1], wx1, wy);
            float e2 = eq4m(slp[q2], wx2, wy);
            float e3 = eq4m(slp[q3], wx3, wy);
            emax = fmaxf(emax, fmaxf(fmaxf(e0, e1), fmaxf(e2, e3)));
            wy += (1.0f / 256.0f);
        }
        for (int o = 16; o; o >>= 1)
            emax = fmaxf(emax, __shfl_xor_sync(0xffffffffu, emax, o));
        int w = threadIdx.x >> 5;
        if ((threadIdx.x & 31) == 0) smx[w] = emax;
        __syncthreads();
        if (threadIdx.x == 0) {
            for (int i = 1; i < 8; ++i) emax = fmaxf(emax, smx[i]);
            atomicMax(&g_maxb2[cc], __float_as_uint(emax));
        }
        __syncthreads();                                 // sl/smx reuse across tiles
    }
    if (threadIdx.x == 0) {
        __threadfence();
        if (atomicInc(&g_done2, LM_BLOCKS - 1u) == LM_BLOCKS - 1u) {     // last block
            for (int ch = 0; ch < NCH; ++ch) {
                if (!g_skip[ch]) {                       // skip channels: A set in phase A
                    unsigned mc = atomicAdd(&g_mcnt[ch], 0u);
                    double mx = (double)__uint_as_float(atomicAdd(&g_maxb2[ch], 0u)) / 255.0;
                    int cond = (mc > 0u) && (mx > 0.0);
                    // vmin of the 2nd normalize is provably 0 whenever cond holds:
                    // out = eq * A + 1/255 for masked pixels.
                    g_A[ch] = cond ? (float)((254.0 / 255.0) / (255.0 * fmax(mx, 1e-12))) : 0.0f;
                }
                g_maxb2[ch] = 0u;                        // reset for next replay
                g_mcnt[ch]  = 0u;
            }
            atomicExch(&g_go2, 0u);                      // reset barrier for next replay
        }
    }
}

// ---------------- K5: recompute eq, final masked normalize, write output --------------
// 64 threads per row x 8 px (uint2) per thread per iteration.
__device__ __forceinline__ float4 out4(unsigned qw, const unsigned* slp,
                                       float wxb, float wy, float A) {
    unsigned q0 = qw & 0xffu, q1 = (qw >> 8) & 0xffu;
    unsigned q2 = (qw >> 16) & 0xffu, q3 = qw >> 24;
    float4 o;
    o.x = fmaf(eq4m(slp[q0], wxb, wy), A, INV255);
    o.y = fmaf(eq4m(slp[q1], wxb + 0.001953125f, wy), A, INV255);
    o.z = fmaf(eq4m(slp[q2], wxb + 0.00390625f, wy), A, INV255);
    o.w = fmaf(eq4m(slp[q3], wxb + 0.005859375f, wy), A, INV255);
    return o;
}

__device__ __forceinline__ void fix4(float4& o, unsigned qw, const float* Xp) {
    if ((qw - 0x01010101u) & ~qw & 0x80808080u) {         // rare: some byte==0 -> check mask
        float4 v = *reinterpret_cast<const float4*>(Xp);
        if (!(qw & 0xffu)       && !(v.x > 0.0f)) o.x = 0.0f;
        if (!(qw & 0xff00u)     && !(v.y > 0.0f)) o.y = 0.0f;
        if (!(qw & 0xff0000u)   && !(v.z > 0.0f)) o.z = 0.0f;
        if (!(qw & 0xff000000u) && !(v.w > 0.0f)) o.w = 0.0f;
    }
}

__global__ __launch_bounds__(256) void k_out(const float* __restrict__ X,
                                             float* __restrict__ out) {
    int tx = blockIdx.x, by = blockIdx.y, c = blockIdx.z;
    __shared__ unsigned sl[2][NBINS];
    load_cmb(sl, c, tx, by);
    __syncthreads();
    float A = g_A[c];
    int c6 = threadIdx.x & 63;
    int colb = tx * 512 + c6 * 8;
    int m0 = (colb - 256) >> 9;
    float wxb = ((float)colb - 255.5f) * (1.0f / 512.0f) - (float)m0;   // exact
    int s = min(max(m0, 0), 7) - tx + 1;
    const unsigned* slp = sl[s];
    int r0 = threadIdx.x >> 6;                            // 0..3
    int row0 = by * 64 + r0;
    float fy0 = ((float)row0 + 0.5f) * (1.0f / 512.0f) - 0.5f;
    float wy = fy0 - floorf(fy0);                         // exact multiple of 2^-10
    size_t base = (size_t)c * NPIX + (size_t)row0 * WIDTH + colb;
#pragma unroll 2
    for (int i = 0; i < 16; ++i) {
        size_t idx = base + (size_t)i * (4 * WIDTH);
        uint2 qq = *reinterpret_cast<const uint2*>(g_xb + idx);
        float4 oA = out4(qq.x, slp, wxb, wy, A);
        float4 oB = out4(qq.y, slp, wxb + 0.0078125f, wy, A);
        fix4(oA, qq.x, X + idx);
        fix4(oB, qq.y, X + idx + 4);
        __stcs(reinterpret_cast<float4*>(out + idx), oA);     // streaming: never re-read
        __stcs(reinterpret_cast<float4*>(out + idx + 4), oB);
        wy += (1.0f / 128.0f);                            // 4 rows per iter; exact
    }
}

// ---------------- launch --------------------------------------------------------------
extern "C" void kernel_launch(void* const* d_in, const int* in_sizes, int n_in,
                              void* d_out, int out_size) {
    const float* X = (const float*)d_in[0];
    float* out = (float*)d_out;
    (void)in_sizes; (void)n_in; (void)out_size;

    dim3 g(8, 64, NCH);
    k_minmax1<<<4096, 256>>>(X);       // + fused fin1 (last block)
    k_binhist<<<g, 256>>>(X);
    k_lutmax<<<LM_BLOCKS, 256>>>();    // LUTs + tiny barrier + hist-rezero + emax + fin2
    k_out<<<g, 256>>>(X, out);
}